// round 9
// baseline (speedup 1.0000x reference)
#include <cuda_runtime.h>
#include <cstdint>

#define BB 32
#define TT 4096
#define DD 512
#define GG 8
#define OO 512
#define NC 16           // chunks over T
#define TC2 256         // tokens per chunk (two 128-token teams)

// Scratch (allocation-free: __device__ globals). Fully overwritten every launch.
__device__ float g_psum[NC * BB * GG * DD];   // 8.4 MB partial sums
__device__ int   g_pcnt[NC * BB * GG];        // partial counts
__device__ float g_mean[BB * GG * DD];        // means [B,G,D]

// ---------------------------------------------------------------------------
// Kernel 1: per-(chunk, batch) partial group sums. 256 threads = 2 teams of
// 128; each team runs the continuous 8-deep gather pipeline over its 128
// tokens (one concatenated group-ordered list, warp-uniform boundaries),
// accumulates into smem, then one combined psum write (halves psum traffic).
// ---------------------------------------------------------------------------
__global__ __launch_bounds__(256) void k_partial(const float* __restrict__ batch,
                                                 const int* __restrict__ types,
                                                 const unsigned int* __restrict__ pad)
{
    __shared__ int            s_type[TC2];
    __shared__ unsigned char  s_val[TC2];
    __shared__ unsigned short s_all[2][128];   // per-team concatenated lists
    __shared__ int            s_boff[2][GG + 1];
    __shared__ int            s_cnt[2][GG];
    __shared__ float4         s_red[2][GG][128];   // 32 KB team partials

    const int c    = blockIdx.x;
    const int b    = blockIdx.y;
    const int tid  = threadIdx.x;
    const int team = tid >> 7;
    const int ttid = tid & 127;
    const int t0   = c * TC2;

    s_type[tid] = types[t0 + tid];
    s_val[tid]  = (pad[b * TT + t0 + tid] == 0u);   // valid = not padded
    __syncthreads();

    // Compaction: warp 0 -> team 0's tokens [0,128); warp 4 -> team 1's [128,256)
    const int wid = tid >> 5;
    if (wid == 0 || wid == 4) {
        const int sub  = wid >> 2;
        const int lane = tid & 31;
        const unsigned lt = (1u << lane) - 1u;
        int cnt[GG];
        #pragma unroll
        for (int g = 0; g < GG; g++) cnt[g] = 0;

        #pragma unroll
        for (int r = 0; r < 4; r++) {
            const int  t  = sub * 128 + r * 32 + lane;
            const int  gt = s_type[t];
            const bool v  = (s_val[t] != 0);
            #pragma unroll
            for (int g = 0; g < GG; g++)
                cnt[g] += __popc(__ballot_sync(0xffffffffu, v && (gt == g)));
        }
        int run[GG];
        {
            int acc = 0;
            #pragma unroll
            for (int g = 0; g < GG; g++) { run[g] = acc; acc += cnt[g]; }
            if (lane == 0) {
                int a2 = 0;
                #pragma unroll
                for (int g = 0; g < GG; g++) { s_boff[sub][g] = a2; s_cnt[sub][g] = cnt[g]; a2 += cnt[g]; }
                s_boff[sub][GG] = a2;
            }
        }
        #pragma unroll
        for (int r = 0; r < 4; r++) {
            const int  t  = sub * 128 + r * 32 + lane;
            const int  gt = s_type[t];
            const bool v  = (s_val[t] != 0);
            #pragma unroll
            for (int g = 0; g < GG; g++) {
                const unsigned m = __ballot_sync(0xffffffffu, v && (gt == g));
                if (v && (gt == g))
                    s_all[sub][run[g] + __popc(m & lt)] = (unsigned short)t;
                run[g] += __popc(m);
            }
        }
    }
    __syncthreads();

    const float4* bp2 = reinterpret_cast<const float4*>(batch)
                      + (size_t)b * TT * (DD / 4) + (size_t)t0 * (DD / 4) + ttid;
    const unsigned short* list = s_all[team];
    const int n = s_boff[team][GG];

    float4 buf[8];
    #pragma unroll
    for (int k = 0; k < 8; k++)
        buf[k] = (k < n) ? __ldcs(&bp2[(int)list[k] * 128])
                         : make_float4(0.f, 0.f, 0.f, 0.f);

    int   g   = 0;
    int   nb  = s_boff[team][1];
    float4 acc = make_float4(0.f, 0.f, 0.f, 0.f);

    while (g < GG && nb == 0) {
        s_red[team][g][ttid] = acc;
        g++;
        nb = (g < GG) ? s_boff[team][g + 1] : 0x7fffffff;
    }

    int i = 0;
    for (; i + 16 <= n; i += 8) {
        #pragma unroll
        for (int k = 0; k < 8; k++) {
            const float4 v = buf[k];
            buf[k] = __ldcs(&bp2[(int)list[i + 8 + k] * 128]);
            acc.x += v.x; acc.y += v.y; acc.z += v.z; acc.w += v.w;
            const int idx1 = i + k + 1;
            while (g < GG && idx1 == nb) {
                s_red[team][g][ttid] = acc;
                acc = make_float4(0.f, 0.f, 0.f, 0.f);
                g++;
                nb = (g < GG) ? s_boff[team][g + 1] : 0x7fffffff;
            }
        }
    }
    for (; i + 8 <= n; i += 8) {
        #pragma unroll
        for (int k = 0; k < 8; k++) {
            const float4 v = buf[k];
            const int j = i + 8 + k;
            if (j < n) buf[k] = __ldcs(&bp2[(int)list[j] * 128]);
            acc.x += v.x; acc.y += v.y; acc.z += v.z; acc.w += v.w;
            const int idx1 = i + k + 1;
            while (g < GG && idx1 == nb) {
                s_red[team][g][ttid] = acc;
                acc = make_float4(0.f, 0.f, 0.f, 0.f);
                g++;
                nb = (g < GG) ? s_boff[team][g + 1] : 0x7fffffff;
            }
        }
    }
    #pragma unroll
    for (int k = 0; k < 8; k++) {
        if (i + k < n) {
            const float4 v = buf[k];
            acc.x += v.x; acc.y += v.y; acc.z += v.z; acc.w += v.w;
            const int idx1 = i + k + 1;
            while (g < GG && idx1 == nb) {
                s_red[team][g][ttid] = acc;
                acc = make_float4(0.f, 0.f, 0.f, 0.f);
                g++;
                nb = (g < GG) ? s_boff[team][g + 1] : 0x7fffffff;
            }
        }
    }
    while (g < GG) {
        s_red[team][g][ttid] = acc;
        acc = make_float4(0.f, 0.f, 0.f, 0.f);
        g++;
    }
    __syncthreads();

    // Combined team write: 8 g x 128 float4, 4 per thread, coalesced
    float4* outp = reinterpret_cast<float4*>(g_psum)
                 + (size_t)(c * BB + b) * GG * (DD / 4);
    #pragma unroll
    for (int k = 0; k < 4; k++) {
        const int idx = tid + k * 256;      // 0..1023
        const int gg  = idx >> 7;
        const int j   = idx & 127;
        const float4 u = s_red[0][gg][j];
        const float4 v = s_red[1][gg][j];
        outp[gg * (DD / 4) + j] = make_float4(u.x + v.x, u.y + v.y, u.z + v.z, u.w + v.w);
    }
    if (tid < GG) g_pcnt[(c * BB + b) * GG + tid] = s_cnt[0][tid] + s_cnt[1][tid];
}

// ---------------------------------------------------------------------------
// Kernel 2: reduce psum -> mean, once. 256 blocks x 128 (MLP 16 per thread).
// ---------------------------------------------------------------------------
__global__ __launch_bounds__(128) void k_mean()
{
    const int bg  = blockIdx.x;     // b*GG+g
    const int tid = threadIdx.x;

    __shared__ float s_inv;
    if (tid == 0) {
        int cnt = 0;
        #pragma unroll
        for (int c = 0; c < NC; c++) cnt += g_pcnt[c * BB * GG + bg];
        s_inv = (cnt > 0) ? (1.0f / (float)cnt) : 0.0f;
    }
    __syncthreads();

    const float4* p = reinterpret_cast<const float4*>(g_psum) + (size_t)bg * (DD / 4) + tid;
    float4 s = make_float4(0.f, 0.f, 0.f, 0.f);
    #pragma unroll
    for (int c = 0; c < NC; c++) {
        const float4 v = p[(size_t)c * BB * GG * (DD / 4)];
        s.x += v.x; s.y += v.y; s.z += v.z; s.w += v.w;
    }
    const float inv = s_inv;
    reinterpret_cast<float4*>(g_mean)[(size_t)bg * (DD / 4) + tid] =
        make_float4(s.x * inv, s.y * inv, s.z * inv, s.w * inv);
}

// ---------------------------------------------------------------------------
// Kernel 3: GEMM. grid (8 ot of 64-o, 2 bh of 16-b, 8 g) = 128 blocks.
// 256 thr: o4 = tid&15 (16 float4 of o), seg = (tid>>4)&3 (128-d slice),
// bq = tid>>6 (4 b's). W duplication cut to 2x (16 MB L2). Seg partials
// reduced via 16 KB smem. smem total = 32KB means + 16KB partials = 48KB.
// ---------------------------------------------------------------------------
__global__ __launch_bounds__(256) void k_gemm(const float* __restrict__ W,
                                              const float* __restrict__ bias,
                                              float* __restrict__ out)
{
    const int ot  = blockIdx.x;           // 64-output o-tile (16 float4)
    const int bh  = blockIdx.y;           // 16-batch half
    const int g   = blockIdx.z;
    const int tid = threadIdx.x;
    const int o4  = tid & 15;
    const int seg = (tid >> 4) & 3;       // d-slice of 128
    const int bq  = tid >> 6;             // owns b = bq*4 .. bq*4+3

    __shared__ float  s_mean[16][DD];     // 32 KB
    __shared__ float4 s_part[4][16][16];  // 16 KB  [seg][b][o4]

    // stage means: 16 b x 128 float4 = 2048 float4, 8 per thread, coalesced
    {
        float4* sm4 = reinterpret_cast<float4*>(s_mean);
        const float4* gm4 = reinterpret_cast<const float4*>(g_mean);
        #pragma unroll
        for (int k = 0; k < 8; k++) {
            const int idx = tid + k * 256;                 // 0..2047
            const int bb  = idx >> 7;                      // 0..15
            const int d4  = idx & 127;
            sm4[idx] = gm4[((size_t)(bh * 16 + bb) * GG + g) * (DD / 4) + d4];
        }
    }
    __syncthreads();

    const float4* W4 = reinterpret_cast<const float4*>(W)
                     + (size_t)g * DD * (OO / 4) + ot * 16 + o4;

    float4 a0 = make_float4(0.f, 0.f, 0.f, 0.f);
    float4 a1 = make_float4(0.f, 0.f, 0.f, 0.f);
    float4 a2 = make_float4(0.f, 0.f, 0.f, 0.f);
    float4 a3 = make_float4(0.f, 0.f, 0.f, 0.f);

    const int d0 = seg * 128;
    const int bb0 = bq * 4;
    #pragma unroll 4
    for (int dd = 0; dd < 128; dd++) {
        const int d = d0 + dd;
        const float4 w = W4[(size_t)d * (OO / 4)];
        const float m0 = s_mean[bb0 + 0][d];
        const float m1 = s_mean[bb0 + 1][d];
        const float m2 = s_mean[bb0 + 2][d];
        const float m3 = s_mean[bb0 + 3][d];
        a0.x += m0 * w.x; a0.y += m0 * w.y; a0.z += m0 * w.z; a0.w += m0 * w.w;
        a1.x += m1 * w.x; a1.y += m1 * w.y; a1.z += m1 * w.z; a1.w += m1 * w.w;
        a2.x += m2 * w.x; a2.y += m2 * w.y; a2.z += m2 * w.z; a2.w += m2 * w.w;
        a3.x += m3 * w.x; a3.y += m3 * w.y; a3.z += m3 * w.z; a3.w += m3 * w.w;
    }

    s_part[seg][bb0 + 0][o4] = a0;
    s_part[seg][bb0 + 1][o4] = a1;
    s_part[seg][bb0 + 2][o4] = a2;
    s_part[seg][bb0 + 3][o4] = a3;
    __syncthreads();

    // Final reduce: thread -> (b = tid>>4, o4p = tid&15)
    {
        const int b   = tid >> 4;
        const int o4p = tid & 15;
        float4 s = make_float4(0.f, 0.f, 0.f, 0.f);
        #pragma unroll
        for (int ss = 0; ss < 4; ss++) {
            const float4 v = s_part[ss][b][o4p];
            s.x += v.x; s.y += v.y; s.z += v.z; s.w += v.w;
        }
        const float4 bi = reinterpret_cast<const float4*>(bias)[g * (OO / 4) + ot * 16 + o4p];
        const size_t obg = (size_t)((bh * 16 + b) * GG + g);
        reinterpret_cast<float4*>(out)[obg * (OO / 4) + ot * 16 + o4p] =
            make_float4(s.x + bi.x, s.y + bi.y, s.z + bi.z, s.w + bi.w);
    }
}

// ---------------------------------------------------------------------------
extern "C" void kernel_launch(void* const* d_in, const int* in_sizes, int n_in,
                              void* d_out, int out_size)
{
    const float*        batch = (const float*)d_in[0];          // [B,T,D] f32
    const float*        W     = (const float*)d_in[1];          // [G,D,OUT] f32
    const float*        bias  = (const float*)d_in[2];          // [G,OUT] f32
    const int*          types = (const int*)d_in[3];            // [T] i32
    const unsigned int* pad   = (const unsigned int*)d_in[4];   // [B,T] mask words
    float*              out   = (float*)d_out;                  // [B,G,OUT] f32

    k_partial<<<dim3(NC, BB), 256>>>(batch, types, pad);
    k_mean<<<BB * GG, 128>>>();
    k_gemm<<<dim3(8, 2, GG), 256>>>(W, bias, out);
}